// round 1
// baseline (speedup 1.0000x reference)
#include <cuda_runtime.h>

#define DEV __device__ __forceinline__

constexpr int B    = 8;
constexpr int N    = 8192;   // gt points per batch
constexpr int M    = 2500;   // pred points per batch
constexpr int PNUM = 10;
constexpr int SPP  = M / PNUM; // 250
constexpr int TILE = 2048;     // gt points per smem tile (32KB)

// Accumulators:
// 0 sumP2G | 1 sumG2P | 2 sE | 3 sG | 4 sInv | 5 sEinv | 6 sE2inv
// 7 sGinv | 8 sG2inv | 9 sF2inv | 10 sStretch | 11 sMc | 12..19 sA[b]
__device__ float g_acc[20];

// ---- packed fp32x2 helpers (Blackwell FFMA2 path) ----
DEV unsigned long long pack2(float lo, float hi) {
    unsigned long long r;
    asm("mov.b64 %0, {%1, %2};" : "=l"(r) : "f"(lo), "f"(hi));
    return r;
}
DEV void unpack2(unsigned long long v, float& lo, float& hi) {
    asm("mov.b64 {%0, %1}, %2;" : "=f"(lo), "=f"(hi) : "l"(v));
}
DEV unsigned long long fma2(unsigned long long a, unsigned long long b, unsigned long long c) {
    unsigned long long d;
    asm("fma.rn.f32x2 %0, %1, %2, %3;" : "=l"(d) : "l"(a), "l"(b), "l"(c));
    return d;
}

// Reusable block reduction (trailing sync so it can be called in a loop).
DEV float blockReduceSum(float v) {
    __shared__ float sred[32];
    #pragma unroll
    for (int o = 16; o > 0; o >>= 1) v += __shfl_down_sync(0xffffffffu, v, o);
    int lane = threadIdx.x & 31, w = threadIdx.x >> 5;
    if (lane == 0) sred[w] = v;
    __syncthreads();
    int nw = (blockDim.x + 31) >> 5;
    v = (threadIdx.x < (unsigned)nw) ? sred[threadIdx.x] : 0.0f;
    if (w == 0) {
        #pragma unroll
        for (int o = 16; o > 0; o >>= 1) v += __shfl_down_sync(0xffffffffu, v, o);
    }
    __syncthreads();
    return v;  // valid in thread 0
}

__global__ void k_init() {
    if (threadIdx.x < 20) g_acc[threadIdx.x] = 0.0f;
}

// ---------------- FFF losses: one pass, partial sums ----------------
__global__ void __launch_bounds__(256) k_fff(const float* __restrict__ fff) {
    int b = blockIdx.y;
    int m = blockIdx.x * blockDim.x + threadIdx.x;
    float v[11];
    #pragma unroll
    for (int i = 0; i < 11; i++) v[i] = 0.0f;
    if (m < M) {
        int idx = (b * M + m) * 3;
        float E = fff[idx], F = fff[idx + 1], G = fff[idx + 2];
        float A2  = fmaxf(E * G - F * F, 0.0f);
        float A   = sqrtf(A2);
        float inv = 1.0f / (A2 + 1e-20f);
        v[0] = E;           v[1] = G;           v[2] = inv;
        v[3] = E * inv;     v[4] = E * E * inv;
        v[5] = G * inv;     v[6] = G * G * inv;
        v[7] = F * F * inv;
        float d = E - G;    v[8] = d * d * inv;
        if ((b & 1) == 0) {  // metric consistency: pair (b, b+1)
            int idx2 = ((b + 1) * M + m) * 3;
            float E2 = fff[idx2], F2 = fff[idx2 + 1], G2 = fff[idx2 + 2];
            float dE = E - E2, dF = F - F2, dG = G - G2;
            v[9] = dE * dE + 2.0f * dF * dF + dG * dG;
        }
        v[10] = A;
    }
    for (int k = 0; k < 11; k++) {
        float s = blockReduceSum(v[k]);
        if (threadIdx.x == 0) {
            if (k < 10) atomicAdd(&g_acc[2 + k], s);
            else        atomicAdd(&g_acc[12 + b], s);
        }
    }
}

// ---------------- Chamfer: pred -> gt  (min over N per pred point) ----------------
__global__ void __launch_bounds__(128) k_p2gt(const float* __restrict__ pred,
                                              const float* __restrict__ gt) {
    __shared__ float4 sg[TILE / 2][2];  // [gx0,gx1,gy0,gy1] [gz0,gz1,|g0|²,|g1|²]
    int b = blockIdx.y;
    int m = blockIdx.x * 128 + threadIdx.x;
    bool valid = (m < M);
    float px = 0.f, py = 0.f, pz = 0.f;
    if (valid) {
        const float* p = pred + (size_t)(b * M + m) * 3;
        px = p[0]; py = p[1]; pz = p[2];
    }
    unsigned long long npx2 = pack2(-2.f * px, -2.f * px);
    unsigned long long npy2 = pack2(-2.f * py, -2.f * py);
    unsigned long long npz2 = pack2(-2.f * pz, -2.f * pz);
    float mn0 = 3.4e38f, mn1 = 3.4e38f;
    const float* gb = gt + (size_t)b * N * 3;

    for (int t0 = 0; t0 < N; t0 += TILE) {
        for (int j = threadIdx.x; j < TILE / 2; j += 128) {
            const float* g = gb + (size_t)(t0 + 2 * j) * 3;
            float x0 = g[0], y0 = g[1], z0 = g[2];
            float x1 = g[3], y1 = g[4], z1 = g[5];
            sg[j][0] = make_float4(x0, x1, y0, y1);
            sg[j][1] = make_float4(z0, z1,
                                   x0 * x0 + y0 * y0 + z0 * z0,
                                   x1 * x1 + y1 * y1 + z1 * z1);
        }
        __syncthreads();
        #pragma unroll 8
        for (int j = 0; j < TILE / 2; j++) {
            float4 a = sg[j][0], c = sg[j][1];
            unsigned long long t = fma2(pack2(a.x, a.y), npx2, pack2(c.z, c.w));
            t = fma2(pack2(a.z, a.w), npy2, t);
            t = fma2(pack2(c.x, c.y), npz2, t);
            float lo, hi; unpack2(t, lo, hi);
            mn0 = fminf(mn0, lo);
            mn1 = fminf(mn1, hi);
        }
        __syncthreads();
    }
    float d = fminf(mn0, mn1) + (px * px + py * py + pz * pz);
    d = fmaxf(d, 0.0f);
    if (!valid) d = 0.0f;
    float s = blockReduceSum(d);
    if (threadIdx.x == 0) atomicAdd(&g_acc[0], s);
}

// ---------------- Chamfer: gt -> pred  (min over M per gt point) ----------------
__global__ void __launch_bounds__(128) k_gt2p(const float* __restrict__ pred,
                                              const float* __restrict__ gt) {
    __shared__ float4 sp[M / 2][2];  // entire pred batch: 1250 packs = 40KB
    int b = blockIdx.y;
    int n = blockIdx.x * 128 + threadIdx.x;  // 64*128 = 8192 exact
    const float* g = gt + (size_t)(b * N + n) * 3;
    float gx = g[0], gy = g[1], gz = g[2];
    unsigned long long ngx2 = pack2(-2.f * gx, -2.f * gx);
    unsigned long long ngy2 = pack2(-2.f * gy, -2.f * gy);
    unsigned long long ngz2 = pack2(-2.f * gz, -2.f * gz);

    const float* pb = pred + (size_t)b * M * 3;
    for (int j = threadIdx.x; j < M / 2; j += 128) {
        const float* p = pb + (size_t)(2 * j) * 3;
        float x0 = p[0], y0 = p[1], z0 = p[2];
        float x1 = p[3], y1 = p[4], z1 = p[5];
        sp[j][0] = make_float4(x0, x1, y0, y1);
        sp[j][1] = make_float4(z0, z1,
                               x0 * x0 + y0 * y0 + z0 * z0,
                               x1 * x1 + y1 * y1 + z1 * z1);
    }
    __syncthreads();

    float mn0 = 3.4e38f, mn1 = 3.4e38f;
    #pragma unroll 5
    for (int j = 0; j < M / 2; j++) {
        float4 a = sp[j][0], c = sp[j][1];
        unsigned long long t = fma2(pack2(a.x, a.y), ngx2, pack2(c.z, c.w));
        t = fma2(pack2(a.z, a.w), ngy2, t);
        t = fma2(pack2(c.x, c.y), ngz2, t);
        float lo, hi; unpack2(t, lo, hi);
        mn0 = fminf(mn0, lo);
        mn1 = fminf(mn1, hi);
    }
    float d = fminf(mn0, mn1) + (gx * gx + gy * gy + gz * gz);
    d = fmaxf(d, 0.0f);
    float s = blockReduceSum(d);
    if (threadIdx.x == 0) atomicAdd(&g_acc[1], s);
}

// ---------------- Final combine ----------------
__global__ void k_final(const float* __restrict__ A_gt, float* __restrict__ out) {
    float BM = (float)(B * M);
    float L_chd = g_acc[0] / BM + g_acc[1] / (float)(B * N);
    float mE = g_acc[2] / BM, mG = g_acc[3] / BM;
    float L_E  = (g_acc[6] - 2.0f * mE * g_acc[5] + mE * mE * g_acc[4]) / BM;
    float L_G  = (g_acc[8] - 2.0f * mG * g_acc[7] + mG * mG * g_acc[4]) / BM;
    float L_F  = g_acc[9]  / BM;
    float L_st = g_acc[10] / BM;
    float L_mc = g_acc[11] / (0.5f * BM);
    float L_ol = 0.0f;
    for (int b = 0; b < B; b++) {
        float at = g_acc[12 + b] * (1.0f / (float)SPP);
        float r  = fmaxf(at - A_gt[b], 0.0f);
        L_ol += r * r;
    }
    L_ol *= (1.0f / (float)B);
    out[0] = L_chd + L_mc + L_F + L_E + L_G + L_st + L_ol;
}

extern "C" void kernel_launch(void* const* d_in, const int* in_sizes, int n_in,
                              void* d_out, int out_size) {
    (void)in_sizes; (void)n_in; (void)out_size;
    const float* pc_gt   = (const float*)d_in[0];
    const float* pc_pred = (const float*)d_in[1];
    const float* fffp    = (const float*)d_in[2];
    const float* A_gt    = (const float*)d_in[3];
    float* out = (float*)d_out;

    k_init<<<1, 32>>>();
    k_fff <<<dim3((M + 255) / 256, B), 256>>>(fffp);
    k_p2gt<<<dim3((M + 127) / 128, B), 128>>>(pc_pred, pc_gt);
    k_gt2p<<<dim3(N / 128, B), 128>>>(pc_pred, pc_gt);
    k_final<<<1, 1>>>(A_gt, out);
}

// round 2
// speedup vs baseline: 1.8640x; 1.8640x over previous
#include <cuda_runtime.h>

#define DEV __device__ __forceinline__

constexpr int B    = 8;
constexpr int N    = 8192;   // gt points per batch
constexpr int M    = 2500;   // pred points per batch
constexpr int PNUM = 10;
constexpr int SPP  = M / PNUM; // 250

// chamfer decomposition
constexpr int QPB    = 512;              // queries per block (4 per thread x 128)
constexpr int GX_P   = (M + QPB - 1) / QPB;   // 5
constexpr int NCHUNK = 8;                // gt candidate chunks (1024 each)
constexpr int CP_P   = N / NCHUNK / 2;   // 512 packs
constexpr int GX_G   = N / QPB;          // 16
constexpr int MCHUNK = 2;                // pred candidate chunks (1250 each)
constexpr int CP_G   = M / MCHUNK / 2;   // 625 packs
constexpr int NBLK_P = GX_P * B * NCHUNK;   // 320
constexpr int NBLK_G = GX_G * B * MCHUNK;   // 256

// Accumulators:
// 0 sumP2G | 1 sumG2P | 2 sE | 3 sG | 4 sInv | 5 sEinv | 6 sE2inv
// 7 sGinv | 8 sG2inv | 9 sF2inv | 10 sStretch | 11 sMc | 12..19 sA[b]
__device__ float    g_acc[20];
__device__ unsigned g_minP[B * M];   // encoded min(||g||^2 - 2 p.g) per pred point
__device__ unsigned g_minG[B * N];   // per gt point

// ---- packed fp32x2 helpers ----
DEV unsigned long long pack2(float lo, float hi) {
    unsigned long long r;
    asm("mov.b64 %0, {%1, %2};" : "=l"(r) : "f"(lo), "f"(hi));
    return r;
}
DEV void unpack2(unsigned long long v, float& lo, float& hi) {
    asm("mov.b64 {%0, %1}, %2;" : "=f"(lo), "=f"(hi) : "l"(v));
}
DEV unsigned long long fma2(unsigned long long a, unsigned long long b, unsigned long long c) {
    unsigned long long d;
    asm("fma.rn.f32x2 %0, %1, %2, %3;" : "=l"(d) : "l"(a), "l"(b), "l"(c));
    return d;
}

// ---- order-preserving float<->uint for atomicMin ----
DEV unsigned encf(float f) {
    unsigned u = __float_as_uint(f);
    return (u & 0x80000000u) ? ~u : (u | 0x80000000u);
}
DEV float decf(unsigned u) {
    return (u & 0x80000000u) ? __uint_as_float(u & 0x7FFFFFFFu)
                             : __uint_as_float(~u);
}

DEV float blockReduceSum(float v) {
    __shared__ float sred[32];
    #pragma unroll
    for (int o = 16; o > 0; o >>= 1) v += __shfl_down_sync(0xffffffffu, v, o);
    int lane = threadIdx.x & 31, w = threadIdx.x >> 5;
    if (lane == 0) sred[w] = v;
    __syncthreads();
    int nw = (blockDim.x + 31) >> 5;
    v = (threadIdx.x < (unsigned)nw) ? sred[threadIdx.x] : 0.0f;
    if (w == 0) {
        #pragma unroll
        for (int o = 16; o > 0; o >>= 1) v += __shfl_down_sync(0xffffffffu, v, o);
    }
    __syncthreads();
    return v;
}

// ---------------- init ----------------
__global__ void k_init() {
    int idx = blockIdx.x * blockDim.x + threadIdx.x;
    if (idx < 20) g_acc[idx] = 0.0f;
    int i2 = idx - 20;
    if (i2 >= 0 && i2 < B * M) g_minP[i2] = 0xFFFFFFFFu;
    int i3 = i2 - B * M;
    if (i3 >= 0 && i3 < B * N) g_minG[i3] = 0xFFFFFFFFu;
}

// ---------------- FFF losses ----------------
__global__ void __launch_bounds__(256) k_fff(const float* __restrict__ fff) {
    int b = blockIdx.y;
    int m = blockIdx.x * blockDim.x + threadIdx.x;
    float v[11];
    #pragma unroll
    for (int i = 0; i < 11; i++) v[i] = 0.0f;
    if (m < M) {
        int idx = (b * M + m) * 3;
        float E = fff[idx], F = fff[idx + 1], G = fff[idx + 2];
        float A2  = fmaxf(E * G - F * F, 0.0f);
        float A   = sqrtf(A2);
        float inv = 1.0f / (A2 + 1e-20f);
        v[0] = E;           v[1] = G;           v[2] = inv;
        v[3] = E * inv;     v[4] = E * E * inv;
        v[5] = G * inv;     v[6] = G * G * inv;
        v[7] = F * F * inv;
        float d = E - G;    v[8] = d * d * inv;
        if ((b & 1) == 0) {
            int idx2 = ((b + 1) * M + m) * 3;
            float E2 = fff[idx2], F2 = fff[idx2 + 1], G2 = fff[idx2 + 2];
            float dE = E - E2, dF = F - F2, dG = G - G2;
            v[9] = dE * dE + 2.0f * dF * dF + dG * dG;
        }
        v[10] = A;
    }
    for (int k = 0; k < 11; k++) {
        float s = blockReduceSum(v[k]);
        if (threadIdx.x == 0) {
            if (k < 10) atomicAdd(&g_acc[2 + k], s);
            else        atomicAdd(&g_acc[12 + b], s);
        }
    }
}

// ---------------- fused chamfer (both directions, chunked candidates) ----------------
__global__ void __launch_bounds__(128) k_chamfer(const float* __restrict__ pred,
                                                 const float* __restrict__ gt) {
    __shared__ float4 sc[CP_G][2];   // max 625 packs = 20KB
    int bid = blockIdx.x;
    int tid = threadIdx.x;

    const float* qb;
    const float* cb;
    unsigned* outp;
    int npacks, q0, qlim;

    if (bid < NBLK_P) {
        int cx = bid % GX_P;
        int b  = (bid / GX_P) & 7;
        int ch = bid / (GX_P * B);
        qb = pred + (size_t)b * M * 3;
        cb = gt   + (size_t)(b * N + ch * (2 * CP_P)) * 3;
        outp = g_minP + b * M;
        npacks = CP_P; q0 = cx * QPB; qlim = M;
    } else {
        int gid = bid - NBLK_P;
        int cx = gid & (GX_G - 1);
        int b  = (gid >> 4) & 7;
        int ch = gid >> 7;
        qb = gt   + (size_t)b * N * 3;
        cb = pred + (size_t)(b * M + ch * (2 * CP_G)) * 3;
        outp = g_minG + b * N;
        npacks = CP_G; q0 = cx * QPB; qlim = N;
    }

    // stage candidate pairs: [x0,x1,y0,y1] [z0,z1,|g0|^2,|g1|^2]
    for (int j = tid; j < npacks; j += 128) {
        const float* g = cb + 6 * j;
        float x0 = g[0], y0 = g[1], z0 = g[2];
        float x1 = g[3], y1 = g[4], z1 = g[5];
        sc[j][0] = make_float4(x0, x1, y0, y1);
        sc[j][1] = make_float4(z0, z1,
                               x0 * x0 + y0 * y0 + z0 * z0,
                               x1 * x1 + y1 * y1 + z1 * z1);
    }

    // 4 queries per thread (strided by 128)
    unsigned long long npx[4], npy[4], npz[4];
    float mn0[4], mn1[4];
    int   mq[4];
    bool  val[4];
    #pragma unroll
    for (int q = 0; q < 4; q++) {
        int m = q0 + q * 128 + tid;
        mq[q] = m; val[q] = (m < qlim);
        float px = 0.f, py = 0.f, pz = 0.f;
        if (val[q]) {
            const float* p = qb + (size_t)m * 3;
            px = p[0]; py = p[1]; pz = p[2];
        }
        npx[q] = pack2(-2.f * px, -2.f * px);
        npy[q] = pack2(-2.f * py, -2.f * py);
        npz[q] = pack2(-2.f * pz, -2.f * pz);
        mn0[q] = 3.4e38f; mn1[q] = 3.4e38f;
    }
    __syncthreads();

    #pragma unroll 2
    for (int j = 0; j < npacks; j++) {
        float4 a = sc[j][0], c = sc[j][1];
        unsigned long long gx2 = pack2(a.x, a.y);
        unsigned long long gy2 = pack2(a.z, a.w);
        unsigned long long gz2 = pack2(c.x, c.y);
        unsigned long long gn2 = pack2(c.z, c.w);
        #pragma unroll
        for (int q = 0; q < 4; q++) {
            unsigned long long t = fma2(gx2, npx[q], gn2);
            t = fma2(gy2, npy[q], t);
            t = fma2(gz2, npz[q], t);
            float lo, hi; unpack2(t, lo, hi);
            mn0[q] = fminf(mn0[q], lo);
            mn1[q] = fminf(mn1[q], hi);
        }
    }

    #pragma unroll
    for (int q = 0; q < 4; q++) {
        if (val[q]) atomicMin(&outp[mq[q]], encf(fminf(mn0[q], mn1[q])));
    }
}

// ---------------- finish: decode mins, add ||q||^2, reduce ----------------
__global__ void __launch_bounds__(128) k_finishP(const float* __restrict__ pred) {
    int b = blockIdx.y;
    int m = blockIdx.x * 128 + threadIdx.x;
    float d = 0.0f;
    if (m < M) {
        float f = decf(g_minP[b * M + m]);
        const float* p = pred + (size_t)(b * M + m) * 3;
        d = fmaxf(f + p[0] * p[0] + p[1] * p[1] + p[2] * p[2], 0.0f);
    }
    float s = blockReduceSum(d);
    if (threadIdx.x == 0) atomicAdd(&g_acc[0], s);
}

__global__ void __launch_bounds__(128) k_finishG(const float* __restrict__ gt) {
    int b = blockIdx.y;
    int n = blockIdx.x * 128 + threadIdx.x;
    float f = decf(g_minG[b * N + n]);
    const float* g = gt + (size_t)(b * N + n) * 3;
    float d = fmaxf(f + g[0] * g[0] + g[1] * g[1] + g[2] * g[2], 0.0f);
    float s = blockReduceSum(d);
    if (threadIdx.x == 0) atomicAdd(&g_acc[1], s);
}

// ---------------- final combine ----------------
__global__ void k_final(const float* __restrict__ A_gt, float* __restrict__ out) {
    float BM = (float)(B * M);
    float L_chd = g_acc[0] / BM + g_acc[1] / (float)(B * N);
    float mE = g_acc[2] / BM, mG = g_acc[3] / BM;
    float L_E  = (g_acc[6] - 2.0f * mE * g_acc[5] + mE * mE * g_acc[4]) / BM;
    float L_G  = (g_acc[8] - 2.0f * mG * g_acc[7] + mG * mG * g_acc[4]) / BM;
    float L_F  = g_acc[9]  / BM;
    float L_st = g_acc[10] / BM;
    float L_mc = g_acc[11] / (0.5f * BM);
    float L_ol = 0.0f;
    for (int b = 0; b < B; b++) {
        float at = g_acc[12 + b] * (1.0f / (float)SPP);
        float r  = fmaxf(at - A_gt[b], 0.0f);
        L_ol += r * r;
    }
    L_ol *= (1.0f / (float)B);
    out[0] = L_chd + L_mc + L_F + L_E + L_G + L_st + L_ol;
}

extern "C" void kernel_launch(void* const* d_in, const int* in_sizes, int n_in,
                              void* d_out, int out_size) {
    (void)in_sizes; (void)n_in; (void)out_size;
    const float* pc_gt   = (const float*)d_in[0];
    const float* pc_pred = (const float*)d_in[1];
    const float* fffp    = (const float*)d_in[2];
    const float* A_gt    = (const float*)d_in[3];
    float* out = (float*)d_out;

    int initN = 20 + B * M + B * N;
    k_init   <<<(initN + 255) / 256, 256>>>();
    k_fff    <<<dim3((M + 255) / 256, B), 256>>>(fffp);
    k_chamfer<<<NBLK_P + NBLK_G, 128>>>(pc_pred, pc_gt);
    k_finishP<<<dim3((M + 127) / 128, B), 128>>>(pc_pred);
    k_finishG<<<dim3(N / 128, B), 128>>>(pc_gt);
    k_final  <<<1, 1>>>(A_gt, out);
}

// round 3
// speedup vs baseline: 1.8886x; 1.0132x over previous
#include <cuda_runtime.h>

#define DEV __device__ __forceinline__

constexpr int B    = 8;
constexpr int N    = 8192;
constexpr int M    = 2500;
constexpr int SPP  = 250;    // M / P(=10)

// chamfer decomposition
constexpr int QPB    = 512;                 // queries per block (4 x 128)
constexpr int GX_P   = (M + QPB - 1) / QPB; // 5
constexpr int NCHUNK = 8;                   // gt candidate chunks
constexpr int CP_P   = N / NCHUNK / 2;      // 512 packs
constexpr int GX_G   = N / QPB;             // 16
constexpr int MCHUNK = 2;                   // pred candidate chunks
constexpr int CP_G   = M / MCHUNK / 2;      // 625 packs
constexpr int NBLK_P = GX_P * B * NCHUNK;   // 320
constexpr int NBLK_G = GX_G * B * MCHUNK;   // 256
constexpr int NBLK_F = 20 * B;              // 160 fff blocks (20 x 128 covers M)
constexpr int NBLK_1 = NBLK_P + NBLK_G + NBLK_F;  // 736

constexpr int FB_P   = (B * M + 511) / 512; // 40 finish blocks (P side)
constexpr int FB_G   = (B * N) / 512;       // 128 finish blocks (G side)

// Partial result arrays — every slot written unconditionally, no init needed.
__device__ float g_partP[NCHUNK * B * M];   // per-chunk min(||g||^2 - 2 p.g)
__device__ float g_partG[MCHUNK * B * N];
__device__ float g_fffp[NBLK_F * 11];       // per-fff-block partial sums
__device__ float g_sum2[FB_P + FB_G];       // finish-block partials

// ---- packed fp32x2 helpers ----
DEV unsigned long long pack2(float lo, float hi) {
    unsigned long long r;
    asm("mov.b64 %0, {%1, %2};" : "=l"(r) : "f"(lo), "f"(hi));
    return r;
}
DEV void unpack2(unsigned long long v, float& lo, float& hi) {
    asm("mov.b64 {%0, %1}, %2;" : "=f"(lo), "=f"(hi) : "l"(v));
}
DEV unsigned long long fma2(unsigned long long a, unsigned long long b, unsigned long long c) {
    unsigned long long d;
    asm("fma.rn.f32x2 %0, %1, %2, %3;" : "=l"(d) : "l"(a), "l"(b), "l"(c));
    return d;
}

DEV float blockReduceSum(float v) {
    __shared__ float sred[32];
    #pragma unroll
    for (int o = 16; o > 0; o >>= 1) v += __shfl_down_sync(0xffffffffu, v, o);
    int lane = threadIdx.x & 31, w = threadIdx.x >> 5;
    if (lane == 0) sred[w] = v;
    __syncthreads();
    int nw = (blockDim.x + 31) >> 5;
    v = (threadIdx.x < (unsigned)nw) ? sred[threadIdx.x] : 0.0f;
    if (w == 0) {
        #pragma unroll
        for (int o = 16; o > 0; o >>= 1) v += __shfl_down_sync(0xffffffffu, v, o);
    }
    __syncthreads();
    return v;  // valid in thread 0
}

// ================= K1: mega kernel — chamfer chunks + fff partials =================
__global__ void __launch_bounds__(128) k_mega(const float* __restrict__ pred,
                                              const float* __restrict__ gt,
                                              const float* __restrict__ fff) {
    int bid = blockIdx.x;
    int tid = threadIdx.x;

    if (bid >= NBLK_P + NBLK_G) {
        // ---------------- fff partial-sums block ----------------
        int fb = bid - (NBLK_P + NBLK_G);
        int b  = fb / 20;
        int m  = (fb % 20) * 128 + tid;
        float v[11];
        #pragma unroll
        for (int i = 0; i < 11; i++) v[i] = 0.0f;
        if (m < M) {
            int idx = (b * M + m) * 3;
            float E = fff[idx], F = fff[idx + 1], G = fff[idx + 2];
            float A2  = fmaxf(E * G - F * F, 0.0f);
            float A   = sqrtf(A2);
            float inv = 1.0f / (A2 + 1e-20f);
            v[0] = E;        v[1] = G;        v[2] = inv;
            v[3] = E * inv;  v[4] = E * E * inv;
            v[5] = G * inv;  v[6] = G * G * inv;
            v[7] = F * F * inv;
            float d = E - G; v[8] = d * d * inv;
            if ((b & 1) == 0) {
                int idx2 = ((b + 1) * M + m) * 3;
                float E2 = fff[idx2], F2 = fff[idx2 + 1], G2 = fff[idx2 + 2];
                float dE = E - E2, dF = F - F2, dG = G - G2;
                v[9] = dE * dE + 2.0f * dF * dF + dG * dG;
            }
            v[10] = A;
        }
        #pragma unroll
        for (int k = 0; k < 11; k++) {
            float s = blockReduceSum(v[k]);
            if (tid == 0) g_fffp[fb * 11 + k] = s;
        }
        return;
    }

    // ---------------- chamfer chunk block ----------------
    __shared__ ulonglong2 sc[2 * CP_G];  // sc[2j]={gx2,gy2}, sc[2j+1]={gz2,gn2}; 20KB

    const float* qb;
    const float* cb;
    float* outp;
    int npacks, q0, qlim;

    if (bid < NBLK_P) {
        int cx = bid % GX_P;
        int b  = (bid / GX_P) & 7;
        int ch = bid / (GX_P * B);
        qb = pred + (size_t)b * M * 3;
        cb = gt   + (size_t)(b * N + ch * (2 * CP_P)) * 3;
        outp = g_partP + ch * (B * M) + b * M;
        npacks = CP_P; q0 = cx * QPB; qlim = M;
    } else {
        int gid = bid - NBLK_P;
        int cx = gid & (GX_G - 1);
        int b  = (gid >> 4) & 7;
        int ch = gid >> 7;
        qb = gt   + (size_t)b * N * 3;
        cb = pred + (size_t)(b * M + ch * (2 * CP_G)) * 3;
        outp = g_partG + ch * (B * N) + b * N;
        npacks = CP_G; q0 = cx * QPB; qlim = N;
    }

    // stage candidate pairs, pre-packed for FFMA2
    for (int j = tid; j < npacks; j += 128) {
        const float* g = cb + 6 * j;
        float x0 = g[0], y0 = g[1], z0 = g[2];
        float x1 = g[3], y1 = g[4], z1 = g[5];
        ulonglong2 u0, u1;
        u0.x = pack2(x0, x1);
        u0.y = pack2(y0, y1);
        u1.x = pack2(z0, z1);
        u1.y = pack2(x0 * x0 + y0 * y0 + z0 * z0,
                     x1 * x1 + y1 * y1 + z1 * z1);
        sc[2 * j]     = u0;
        sc[2 * j + 1] = u1;
    }

    // 4 queries per thread
    unsigned long long npx[4], npy[4], npz[4];
    float mn0[4], mn1[4];
    int   mq[4];
    bool  val[4];
    #pragma unroll
    for (int q = 0; q < 4; q++) {
        int m = q0 + q * 128 + tid;
        mq[q] = m; val[q] = (m < qlim);
        float px = 0.f, py = 0.f, pz = 0.f;
        if (val[q]) {
            const float* p = qb + (size_t)m * 3;
            px = p[0]; py = p[1]; pz = p[2];
        }
        npx[q] = pack2(-2.f * px, -2.f * px);
        npy[q] = pack2(-2.f * py, -2.f * py);
        npz[q] = pack2(-2.f * pz, -2.f * pz);
        mn0[q] = 3.4e38f; mn1[q] = 3.4e38f;
    }
    __syncthreads();

    #pragma unroll 2
    for (int j = 0; j < npacks; j++) {
        ulonglong2 u0 = sc[2 * j];
        ulonglong2 u1 = sc[2 * j + 1];
        #pragma unroll
        for (int q = 0; q < 4; q++) {
            unsigned long long t = fma2(u0.x, npx[q], u1.y);
            t = fma2(u0.y, npy[q], t);
            t = fma2(u1.x, npz[q], t);
            float lo, hi; unpack2(t, lo, hi);
            mn0[q] = fminf(mn0[q], lo);
            mn1[q] = fminf(mn1[q], hi);
        }
    }

    #pragma unroll
    for (int q = 0; q < 4; q++) {
        if (val[q]) outp[mq[q]] = fminf(mn0[q], mn1[q]);
    }
}

// ================= K2: finish — min over chunks, add norms, partial sums =========
__global__ void __launch_bounds__(512) k_finish(const float* __restrict__ pred,
                                                const float* __restrict__ gt) {
    int bid = blockIdx.x;
    int tid = threadIdx.x;
    float d = 0.0f;
    if (bid < FB_P) {
        int qi = bid * 512 + tid;          // [0, B*M)
        if (qi < B * M) {
            float f = g_partP[qi];
            #pragma unroll
            for (int ch = 1; ch < NCHUNK; ch++)
                f = fminf(f, g_partP[ch * (B * M) + qi]);
            const float* p = pred + (size_t)qi * 3;
            d = fmaxf(f + p[0] * p[0] + p[1] * p[1] + p[2] * p[2], 0.0f);
        }
    } else {
        int gi = (bid - FB_P) * 512 + tid;  // [0, B*N), exact
        float f = fminf(g_partG[gi], g_partG[B * N + gi]);
        const float* g = gt + (size_t)gi * 3;
        d = fmaxf(f + g[0] * g[0] + g[1] * g[1] + g[2] * g[2], 0.0f);
    }
    float s = blockReduceSum(d);
    if (tid == 0) g_sum2[bid] = s;
}

// ================= K3: final combine =================
__global__ void __launch_bounds__(512) k_final(const float* __restrict__ A_gt,
                                               float* __restrict__ out) {
    int tid = threadIdx.x;
    __shared__ float sA[NBLK_F];
    __shared__ float acc[12];

    // fff sums (k = 0..9)
    #pragma unroll
    for (int k = 0; k < 10; k++) {
        float v = (tid < NBLK_F) ? g_fffp[tid * 11 + k] : 0.0f;
        float s = blockReduceSum(v);
        if (tid == 0) acc[k] = s;
    }
    // chamfer sums
    {
        float v = (tid < FB_P) ? g_sum2[tid] : 0.0f;
        float s = blockReduceSum(v);
        if (tid == 0) acc[10] = s;
        v = (tid < FB_G) ? g_sum2[FB_P + tid] : 0.0f;
        s = blockReduceSum(v);
        if (tid == 0) acc[11] = s;
    }
    // per-batch A partials
    if (tid < NBLK_F) sA[tid] = g_fffp[tid * 11 + 10];
    __syncthreads();

    if (tid == 0) {
        float BM = (float)(B * M);
        float L_chd = acc[10] / BM + acc[11] / (float)(B * N);
        float sE = acc[0], sG = acc[1], sInv = acc[2];
        float sEinv = acc[3], sE2inv = acc[4], sGinv = acc[5], sG2inv = acc[6];
        float sF2inv = acc[7], sStretch = acc[8], sMc = acc[9];
        float mE = sE / BM, mG = sG / BM;
        float L_E  = (sE2inv - 2.0f * mE * sEinv + mE * mE * sInv) / BM;
        float L_G  = (sG2inv - 2.0f * mG * sGinv + mG * mG * sInv) / BM;
        float L_F  = sF2inv  / BM;
        float L_st = sStretch / BM;
        float L_mc = sMc / (0.5f * BM);
        float L_ol = 0.0f;
        for (int b = 0; b < B; b++) {
            float at = 0.0f;
            for (int j = 0; j < 20; j++) at += sA[b * 20 + j];
            at *= (1.0f / (float)SPP);
            float r = fmaxf(at - A_gt[b], 0.0f);
            L_ol += r * r;
        }
        L_ol *= (1.0f / (float)B);
        out[0] = L_chd + L_mc + L_F + L_E + L_G + L_st + L_ol;
    }
}

extern "C" void kernel_launch(void* const* d_in, const int* in_sizes, int n_in,
                              void* d_out, int out_size) {
    (void)in_sizes; (void)n_in; (void)out_size;
    const float* pc_gt   = (const float*)d_in[0];
    const float* pc_pred = (const float*)d_in[1];
    const float* fffp    = (const float*)d_in[2];
    const float* A_gt    = (const float*)d_in[3];
    float* out = (float*)d_out;

    k_mega  <<<NBLK_1, 128>>>(pc_pred, pc_gt, fffp);
    k_finish<<<FB_P + FB_G, 512>>>(pc_pred, pc_gt);
    k_final <<<1, 512>>>(A_gt, out);
}